// round 6
// baseline (speedup 1.0000x reference)
#include <cuda_runtime.h>

// Fused depthwise conv: y = gauss_valid(fd_valid(x)) == one 13-tap valid FIR.
// Composed kernel is SYMMETRIC (both fd and gauss are), so only 7 unique
// weights: out[j] = sum_{k=0..5} w[k]*(x[j+k]+x[j+12-k]) + w[6]*x[j+6].
//
// x: [8,4,T] f32 -> 32 rows, T = 1048576. out rows: T-12.
//
// R4: VPT=8 direct-LDG streaming. 5 front-batched LDG.128 per thread
// (2.5x L1 amplification, down from 4x), 7 weight regs (symmetry), forced
// >=5 CTAs/SM via launch bounds for 40-warp occupancy.

#define BLOCK 256
#define VPT   8
#define TILE  (BLOCK * VPT)   // 2048 outputs per block

__global__ __launch_bounds__(BLOCK, 5)
void fused_fir13_v8(const float* __restrict__ x,
                    const float* __restrict__ fd,   // 5 taps
                    const float* __restrict__ gk,   // 9 taps
                    float* __restrict__ out,
                    int T, int Tout, int tilesPerRow)
{
    __shared__ float wsh[7];

    const int tid  = threadIdx.x;
    const int bid  = blockIdx.x;
    const int row  = bid / tilesPerRow;
    const int tile = bid - row * tilesPerRow;

    const long long xb = (long long)row * T;
    const long long ob = (long long)row * Tout;
    const int gb = tile * TILE + tid * VPT;      // first output index

    // ---- Front-batch data loads: 20 floats = 5 LDG.128 (32B-aligned) ----
    float r[VPT + 12];
    const bool inner = (gb + 20 <= T);
    if (inner) {
        #pragma unroll
        for (int v = 0; v < 5; ++v) {
            float4 f = *(const float4*)(x + xb + gb + 4 * v);
            r[4*v+0] = f.x; r[4*v+1] = f.y; r[4*v+2] = f.z; r[4*v+3] = f.w;
        }
    } else {
        #pragma unroll
        for (int i = 0; i < 20; ++i) {
            const int gi = gb + i;
            r[i] = (gi < T) ? x[xb + gi] : 0.f;
        }
    }

    // ---- Compose symmetric half-kernel (overlaps in-flight data LDGs) ----
    // w13[k] = sum_{i+j=k} fd[i]*gk[j];  wsh[k] = w13[k] for k=0..6.
    if (tid < 7) {
        float acc = 0.f;
        const int hi = tid < 4 ? tid : 4;
        for (int i = 0; i <= hi; ++i) acc += fd[i] * gk[tid - i];
        wsh[tid] = acc;
    }
    __syncthreads();

    float w[7];
    #pragma unroll
    for (int k = 0; k < 7; ++k) w[k] = wsh[k];

    // ---- Compute 8 outputs ----
    float a[VPT];
    #pragma unroll
    for (int j = 0; j < VPT; ++j) {
        float acc = w[6] * r[j + 6];
        #pragma unroll
        for (int k = 0; k < 6; ++k)
            acc = fmaf(w[k], r[j + k] + r[j + 12 - k], acc);
        a[j] = acc;
    }

    // ---- Store ----
    if (gb + VPT <= Tout) {
        *(float4*)(out + ob + gb)     = make_float4(a[0], a[1], a[2], a[3]);
        *(float4*)(out + ob + gb + 4) = make_float4(a[4], a[5], a[6], a[7]);
    } else {
        #pragma unroll
        for (int v = 0; v < VPT; ++v)
            if (gb + v < Tout) out[ob + gb + v] = a[v];
    }
}

extern "C" void kernel_launch(void* const* d_in, const int* in_sizes, int n_in,
                              void* d_out, int out_size)
{
    const float* x  = (const float*)d_in[0];
    const float* fd = (const float*)d_in[1];   // 5 elements
    const float* gk = (const float*)d_in[2];   // 9 elements
    float* out = (float*)d_out;

    const int ROWS = 32;                       // 8 * 4
    const int T    = in_sizes[0] / ROWS;       // 1048576
    const int Tout = T - 12;                   // 1048564

    const int tilesPerRow = (Tout + TILE - 1) / TILE;   // 512
    const int blocks = ROWS * tilesPerRow;              // 16384

    fused_fir13_v8<<<blocks, BLOCK>>>(x, fd, gk, out, T, Tout, tilesPerRow);
}

// round 8
// speedup vs baseline: 1.4723x; 1.4723x over previous
#include <cuda_runtime.h>

// Fused depthwise conv: y = gauss_valid(fd_valid(x)) == one 13-tap valid FIR.
// Composed kernel is SYMMETRIC: out[j] = sum_{k<6} w[k]*(x[j+k]+x[j+12-k])
//                                        + w[6]*x[j+6].
//
// x: [8,4,T] f32 -> 32 rows, T = 1048576. out rows: Tout = T-12.
//
// R5: persistent grid-stride kernel. R3's proven access pattern (VPT=4,
// 16B lane stride, fully-coalesced LDG.128, 2 groups = 8 loads in flight)
// + symmetric weights (reg cut) + launch_bounds(256,5) for 40 warps/SM
// + no per-tile barrier (weights composed once, before the loop).

#define BLOCK  256
#define GROUPS 2
#define GTILE  (BLOCK * 4)        // 1024 outputs per group
#define TILE   (GTILE * GROUPS)   // 2048 outputs per tile

__global__ __launch_bounds__(BLOCK, 5)
void fused_fir13_persist(const float* __restrict__ x,
                         const float* __restrict__ fd,   // 5 taps
                         const float* __restrict__ gk,   // 9 taps
                         float* __restrict__ out,
                         int T, int Tout, int tilesPerRow, int tilesTotal)
{
    __shared__ float wsh[7];

    const int tid = threadIdx.x;

    // Compose symmetric half-kernel once per CTA.
    if (tid < 7) {
        float acc = 0.f;
        const int hi = tid < 4 ? tid : 4;
        for (int i = 0; i <= hi; ++i) acc += fd[i] * gk[tid - i];
        wsh[tid] = acc;
    }
    __syncthreads();

    float w[7];
    #pragma unroll
    for (int k = 0; k < 7; ++k) w[k] = wsh[k];

    for (int t = blockIdx.x; t < tilesTotal; t += gridDim.x) {
        const int row  = t / tilesPerRow;
        const int tile = t - row * tilesPerRow;

        const long long xb = (long long)row * T;
        const long long ob = (long long)row * Tout;
        const int start = tile * TILE;

        // ---- Front-batch all loads: 8 coalesced LDG.128 in flight ----
        float r[GROUPS][16];
        #pragma unroll
        for (int q = 0; q < GROUPS; ++q) {
            const int gb = start + q * GTILE + tid * 4;
            if (gb + 16 <= T) {
                #pragma unroll
                for (int v = 0; v < 4; ++v) {
                    float4 f = *(const float4*)(x + xb + gb + 4 * v);
                    r[q][4*v+0] = f.x; r[q][4*v+1] = f.y;
                    r[q][4*v+2] = f.z; r[q][4*v+3] = f.w;
                }
            } else {
                #pragma unroll
                for (int i = 0; i < 16; ++i) {
                    const int gi = gb + i;
                    r[q][i] = (gi < T) ? x[xb + gi] : 0.f;
                }
            }
        }

        // ---- Compute + store per group ----
        #pragma unroll
        for (int q = 0; q < GROUPS; ++q) {
            const int gb = start + q * GTILE + tid * 4;
            float a[4];
            #pragma unroll
            for (int j = 0; j < 4; ++j) {
                float acc = w[6] * r[q][j + 6];
                #pragma unroll
                for (int k = 0; k < 6; ++k)
                    acc = fmaf(w[k], r[q][j + k] + r[q][j + 12 - k], acc);
                a[j] = acc;
            }
            if (gb + 4 <= Tout) {
                *(float4*)(out + ob + gb) = make_float4(a[0], a[1], a[2], a[3]);
            } else {
                #pragma unroll
                for (int v = 0; v < 4; ++v)
                    if (gb + v < Tout) out[ob + gb + v] = a[v];
            }
        }
    }
}

extern "C" void kernel_launch(void* const* d_in, const int* in_sizes, int n_in,
                              void* d_out, int out_size)
{
    const float* x  = (const float*)d_in[0];
    const float* fd = (const float*)d_in[1];   // 5 elements
    const float* gk = (const float*)d_in[2];   // 9 elements
    float* out = (float*)d_out;

    const int ROWS = 32;                       // 8 * 4
    const int T    = in_sizes[0] / ROWS;       // 1048576
    const int Tout = T - 12;                   // 1048564

    const int tilesPerRow = (Tout + TILE - 1) / TILE;   // 512
    const int tilesTotal  = ROWS * tilesPerRow;         // 16384

    const int SMS = 148, CTAS_PER_SM = 5;
    int blocks = SMS * CTAS_PER_SM;                     // 740 persistent CTAs
    if (blocks > tilesTotal) blocks = tilesTotal;

    fused_fir13_persist<<<blocks, BLOCK>>>(x, fd, gk, out,
                                           T, Tout, tilesPerRow, tilesTotal);
}